// round 9
// baseline (speedup 1.0000x reference)
#include <cuda_runtime.h>
#include <cuda_bf16.h>
#include <cstdint>

// LorenzSDE ShARK integrator, B = 4,194,304, 5 steps, additive noise.
// HBM-bound streaming (604 MB). Persistent CTAs + double-buffered cp.async
// pipeline: prefetch tile n+1 while computing tile n, so the DRAM request
// stream never drains across compute/epilogue phases.

#define BATCH_TOTAL 4194304
#define NSTEP 5
#define TILE 128                       // batch elements per tile
#define BLK 128                        // threads per CTA
#define NTILES (BATCH_TOTAL / TILE)    // 32768
#define GRID 888                       // 148 SMs * 6 CTAs

__device__ __forceinline__ void cp16(unsigned int saddr, const void* gptr) {
    asm volatile("cp.async.cg.shared.global [%0], [%1], 16;\n"
                 :: "r"(saddr), "l"(gptr));
}
__device__ __forceinline__ void cp_commit() {
    asm volatile("cp.async.commit_group;\n" ::: "memory");
}
__device__ __forceinline__ void cp_wait1() {
    asm volatile("cp.async.wait_group 1;\n" ::: "memory");
}

__device__ __forceinline__ void lorenz_drift(float x, float y, float z,
                                             float& fx, float& fy, float& fz) {
    fx = 10.0f * (y - x);
    fy = x * (28.0f - z) - y;
    fz = x * y - (8.0f / 3.0f) * z;
}

__global__ __launch_bounds__(BLK)
void lorenz_shark_pipe(const float* __restrict__ x,
                       const float* __restrict__ dW,
                       const float* __restrict__ dH,
                       float* __restrict__ out) {
    __shared__ __align__(16) float s_w[2][TILE * 15];  // 2 x 7680 B
    __shared__ __align__(16) float s_h[2][TILE * 15];  // 2 x 7680 B
    __shared__ __align__(16) float s_x[2][TILE * 3];   // 2 x 1536 B
    __shared__ __align__(16) float s_o[TILE * 3];      //     1536 B

    const int tid = threadIdx.x;

    // ---- prefetch one tile into buffer `buf` (16B cp.async, coalesced) ----
    auto prefetch = [&](int t, int buf) {
        const char* wg = (const char*)dW + (size_t)t * (TILE * 15 * 4);
        const char* hg = (const char*)dH + (size_t)t * (TILE * 15 * 4);
        const char* xg = (const char*)x  + (size_t)t * (TILE * 3 * 4);
        unsigned int ws = (unsigned int)__cvta_generic_to_shared(&s_w[buf][0]);
        unsigned int hs = (unsigned int)__cvta_generic_to_shared(&s_h[buf][0]);
        unsigned int xs = (unsigned int)__cvta_generic_to_shared(&s_x[buf][0]);
        // 480 float4 each for w/h = 3*BLK + 96; 96 float4 for x
#pragma unroll
        for (int i = 0; i < 3; i++) {
            int o = (tid + i * BLK) * 16;
            cp16(ws + o, wg + o);
            cp16(hs + o, hg + o);
        }
        if (tid < (TILE * 3) / 4) {                    // 96
            int o3 = (tid + 3 * BLK) * 16;
            cp16(ws + o3, wg + o3);
            cp16(hs + o3, hg + o3);
            cp16(xs + tid * 16, xg + tid * 16);
        }
    };

    const float dt    = 0.01f;
    const float cW    = 0.2f;            // NOISE * sqrt(dt)
    const float cH    = 0.057735026919f; // NOISE * sqrt(dt/12)
    const float c56dt = (5.0f / 6.0f) * 0.01f;
    const float c56   = 5.0f / 6.0f;

    int t = blockIdx.x;
    int buf = 0;
    prefetch(t, 0);
    cp_commit();

    for (; t < NTILES; t += GRID) {
        const int nxt = t + GRID;
        if (nxt < NTILES) prefetch(nxt, buf ^ 1);
        cp_commit();            // empty group on last iteration (legal, no-op)
        cp_wait1();             // oldest (current tile's) group complete
        __syncthreads();

        // ---- compute: all 5 steps in registers -------------------------
        float y0 = s_x[buf][tid * 3 + 0];
        float y1 = s_x[buf][tid * 3 + 1];
        float y2 = s_x[buf][tid * 3 + 2];

#pragma unroll
        for (int s = 0; s < NSTEP; s++) {
            const int wb = tid * (NSTEP * 3) + s * 3;  // stride 15: conflict-free
            float w0 = cW * s_w[buf][wb + 0];
            float w1 = cW * s_w[buf][wb + 1];
            float w2 = cW * s_w[buf][wb + 2];
            float h0 = cH * s_h[buf][wb + 0];
            float h1 = cH * s_h[buf][wb + 1];
            float h2 = cH * s_h[buf][wb + 2];

            float z0 = y0 + h0, z1 = y1 + h1, z2 = y2 + h2;
            float f10, f11, f12;
            lorenz_drift(z0, z1, z2, f10, f11, f12);

            float u0 = y0 + c56dt * f10 + c56 * w0 + h0;
            float u1 = y1 + c56dt * f11 + c56 * w1 + h1;
            float u2 = y2 + c56dt * f12 + c56 * w2 + h2;
            float f20, f21, f22;
            lorenz_drift(u0, u1, u2, f20, f21, f22);

            y0 = y0 + dt * (0.4f * f10 + 0.6f * f20) + w0;
            y1 = y1 + dt * (0.4f * f11 + 0.6f * f21) + w1;
            y2 = y2 + dt * (0.4f * f12 + 0.6f * f22) + w2;
        }

        // ---- coalesced store via s_o (never a cp.async target) ---------
        s_o[tid * 3 + 0] = y0;
        s_o[tid * 3 + 1] = y1;
        s_o[tid * 3 + 2] = y2;
        __syncthreads();

        float4* o4 = (float4*)(out + (size_t)t * (TILE * 3));
        if (tid < (TILE * 3) / 4) o4[tid] = ((const float4*)s_o)[tid];

        buf ^= 1;
        // s_o read (STG) vs next-iter s_o write: ordered by next-iter's
        // first __syncthreads(); old-buf smem reads vs next-iter prefetch
        // writes: ordered by this iteration's second __syncthreads() plus
        // the wait_group 1 pattern (prefetch into buf^1 only).
    }
}

extern "C" void kernel_launch(void* const* d_in, const int* in_sizes, int n_in,
                              void* d_out, int out_size) {
    const float* x  = (const float*)d_in[0];   // [B, 3]
    const float* dW = (const float*)d_in[1];   // [B, 5, 3]
    const float* dH = (const float*)d_in[2];   // [B, 5, 3]
    float* out = (float*)d_out;                // [B, 3]

    lorenz_shark_pipe<<<GRID, BLK>>>(x, dW, dH, out);
}

// round 13
// speedup vs baseline: 1.0672x; 1.0672x over previous
#include <cuda_runtime.h>
#include <cuda_bf16.h>
#include <cstdint>

// LorenzSDE ShARK integrator, B = 4,194,304, 5 steps, additive noise.
// HBM-bound streaming (604 MB). One-shot CTAs (pipeline attempt regressed:
// it cut occupancy). Lever here is concurrency: 128-thread CTAs, 12/SM
// (reg-capped via launch_bounds, smem trimmed to 15.4KB by reusing s_w for
// the output stage and loading x directly), streaming cache hints.

#define BATCH_TOTAL 4194304
#define NSTEP 5
#define TILE 128                       // batch elements per tile == threads
#define BLK 128
#define NTILES (BATCH_TOTAL / TILE)    // 32768

__device__ __forceinline__ void lorenz_drift(float x, float y, float z,
                                             float& fx, float& fy, float& fz) {
    fx = 10.0f * (y - x);
    fy = x * (28.0f - z) - y;
    fz = x * y - (8.0f / 3.0f) * z;
}

__global__ __launch_bounds__(BLK, 12)
void lorenz_shark_kernel(const float* __restrict__ x,
                         const float* __restrict__ dW,
                         const float* __restrict__ dH,
                         float* __restrict__ out) {
    __shared__ __align__(16) float s_w[TILE * 15];   // 7680 B
    __shared__ __align__(16) float s_h[TILE * 15];   // 7680 B

    const int tid = threadIdx.x;
    const size_t base = (size_t)blockIdx.x * TILE;

    // ---- coalesced float4 staging of dW/dH (480 float4 each) ----------
    const float4* __restrict__ w4 = (const float4*)(dW + base * 15);
    const float4* __restrict__ h4 = (const float4*)(dH + base * 15);
    float4* sw4 = (float4*)s_w;
    float4* sh4 = (float4*)s_h;
#pragma unroll
    for (int i = 0; i < 3; i++) {
        sw4[tid + i * BLK] = __ldcs(&w4[tid + i * BLK]);
        sh4[tid + i * BLK] = __ldcs(&h4[tid + i * BLK]);
    }
    if (tid < (TILE * 15 / 4) - 3 * BLK) {           // 96 tail float4 each
        sw4[tid + 3 * BLK] = __ldcs(&w4[tid + 3 * BLK]);
        sh4[tid + 3 * BLK] = __ldcs(&h4[tid + 3 * BLK]);
    }

    // ---- x loaded directly: warp covers 384 contiguous bytes per LDG ---
    float y0 = __ldcs(x + (base + tid) * 3 + 0);
    float y1 = __ldcs(x + (base + tid) * 3 + 1);
    float y2 = __ldcs(x + (base + tid) * 3 + 2);
    __syncthreads();

    const float dt    = 0.01f;
    const float cW    = 0.2f;            // NOISE * sqrt(dt)
    const float cH    = 0.057735026919f; // NOISE * sqrt(dt/12)
    const float c56dt = (5.0f / 6.0f) * 0.01f;
    const float c56   = 5.0f / 6.0f;

#pragma unroll
    for (int s = 0; s < NSTEP; s++) {
        const int wb = tid * (NSTEP * 3) + s * 3;    // stride 15: conflict-free
        float w0 = cW * s_w[wb + 0];
        float w1 = cW * s_w[wb + 1];
        float w2 = cW * s_w[wb + 2];
        float h0 = cH * s_h[wb + 0];
        float h1 = cH * s_h[wb + 1];
        float h2 = cH * s_h[wb + 2];

        // z1 = y + h
        float z0 = y0 + h0, z1 = y1 + h1, z2 = y2 + h2;
        float f10, f11, f12;
        lorenz_drift(z0, z1, z2, f10, f11, f12);

        // z2 = y + (5/6)dt*f1 + (5/6)*w + h
        float u0 = y0 + c56dt * f10 + c56 * w0 + h0;
        float u1 = y1 + c56dt * f11 + c56 * w1 + h1;
        float u2 = y2 + c56dt * f12 + c56 * w2 + h2;
        float f20, f21, f22;
        lorenz_drift(u0, u1, u2, f20, f21, f22);

        // y = y + dt*(0.4*f1 + 0.6*f2) + w
        y0 = y0 + dt * (0.4f * f10 + 0.6f * f20) + w0;
        y1 = y1 + dt * (0.4f * f11 + 0.6f * f21) + w1;
        y2 = y2 + dt * (0.4f * f12 + 0.6f * f22) + w2;
    }

    // ---- reuse s_w for output staging (all s_w reads done -> sync) -----
    __syncthreads();
    s_w[tid * 3 + 0] = y0;
    s_w[tid * 3 + 1] = y1;
    s_w[tid * 3 + 2] = y2;
    __syncthreads();

    float4* o4 = (float4*)(out + base * 3);
    if (tid < (TILE * 3) / 4)                        // 96 float4
        __stcs(&o4[tid], ((const float4*)s_w)[tid]);
}

extern "C" void kernel_launch(void* const* d_in, const int* in_sizes, int n_in,
                              void* d_out, int out_size) {
    const float* x  = (const float*)d_in[0];   // [B, 3]
    const float* dW = (const float*)d_in[1];   // [B, 5, 3]
    const float* dH = (const float*)d_in[2];   // [B, 5, 3]
    float* out = (float*)d_out;                // [B, 3]

    lorenz_shark_kernel<<<NTILES, BLK>>>(x, dW, dH, out);
}